// round 6
// baseline (speedup 1.0000x reference)
#include <cuda_runtime.h>
#include <cstdint>

#define B_   2
#define N_   8
#define C_   64
#define H_   192
#define W_   256
#define V_   200000
#define HW_  (H_*W_)
#define R_   (N_*HW_)          // 393216
#define ROWS_ (B_*V_)          // 400000
#define OUT_ 128

// Scratch: zero-initialized at module load; the GEMM kernel re-zeroes exactly
// what it reads, so every kernel_launch invocation sees clean state.
__device__ float g_sums[(size_t)ROWS_*C_];   // 102.4 MB
__device__ float g_cnt[ROWS_];

__device__ __forceinline__ uint32_t f2tf32(float x){
    uint32_t r;
    asm("cvt.rna.tf32.f32 %0, %1;" : "=r"(r) : "f"(x));
    return r;
}

#define MMA_TF32(c, a0,a1,a2,a3, b0,b1)                                       \
    asm volatile("mma.sync.aligned.m16n8k8.row.col.f32.tf32.tf32.f32 "        \
        "{%0,%1,%2,%3}, {%4,%5,%6,%7}, {%8,%9}, {%0,%1,%2,%3};"               \
        : "+f"(c[0]), "+f"(c[1]), "+f"(c[2]), "+f"(c[3])                      \
        : "r"(a0), "r"(a1), "r"(a2), "r"(a3), "r"(b0), "r"(b1))

// ---------------------------------------------------------------------------
// Kernel 1: ray directions.  d_i = R[:,0]*uu + R[:,1]*vv + R[:,2], normalized.
// ---------------------------------------------------------------------------
__global__ void rays_kernel(const float* __restrict__ pose,
                            const float* __restrict__ intr,
                            float* __restrict__ dout)
{
    int i = blockIdx.x*blockDim.x + threadIdx.x;
    if (i >= B_*R_) return;
    int w  = i % W_;
    int h  = (i / W_) % H_;
    int bn = i / HW_;                 // b*N + n
    const float* p  = pose + bn*16;
    const float* it = intr + bn*6;
    float uu = ((float)w - it[2]) / it[0];
    float vv = ((float)h - it[3]) / it[1];
    float dx = p[0]*uu + p[1]*vv + p[2];
    float dy = p[4]*uu + p[5]*vv + p[6];
    float dz = p[8]*uu + p[9]*vv + p[10];
    float rn = rsqrtf(dx*dx + dy*dy + dz*dz);
    dout[3*i+0] = dx*rn;
    dout[3*i+1] = dy*rn;
    dout[3*i+2] = dz*rn;
}

// ---------------------------------------------------------------------------
// Kernel 2: masked scatter-add of per-pixel 64-ch features into g_sums, and
// hit counts into g_cnt.  grid.y = q selects a 16-channel slice so global
// feature loads stay coalesced (consecutive threads = consecutive pixels).
// ---------------------------------------------------------------------------
__global__ void scatter_kernel(const float* __restrict__ feat,
                               const int*   __restrict__ vids,
                               const unsigned* __restrict__ mask)
{
    int idx = blockIdx.x*blockDim.x + threadIdx.x;
    if (idx >= B_*R_) return;
    if (mask[idx] == 0u) return;          // works for float32 1.0 or int32 1
    int q   = blockIdx.y;                 // 0..3 -> channels q*16 .. q*16+15
    int b   = idx / R_;
    int vid = vids[idx];
    if (q == 0) atomicAdd(&g_cnt[b*V_ + vid], 1.0f);
    int bn = idx / HW_;                   // (b*N + n)
    int hw = idx % HW_;
    const float* fp = feat + ((size_t)bn*C_ + q*16)*HW_ + hw;
    float* sp = g_sums + (size_t)(b*V_ + vid)*C_ + q*16;
    #pragma unroll
    for (int cg = 0; cg < 4; cg++){
        float x0 = fp[(4*cg+0)*HW_];
        float x1 = fp[(4*cg+1)*HW_];
        float x2 = fp[(4*cg+2)*HW_];
        float x3 = fp[(4*cg+3)*HW_];
        asm volatile("red.global.add.v4.f32 [%0], {%1, %2, %3, %4};"
                     :: "l"(sp + 4*cg), "f"(x0), "f"(x1), "f"(x2), "f"(x3)
                     : "memory");
    }
}

// ---------------------------------------------------------------------------
// Kernel 3: out[row,:] = (sums[row,:]/max(cnt,1)) @ W[0:64,:] + conf*W[64,:] + b
// tf32 MMA with hi/lo split (3 MMAs) => effectively fp32 accuracy.
// Each warp owns a 16-row x 128-col tile; block = 8 warps = 128 rows.
// Also resets g_sums / g_cnt to zero for the next graph replay.
// ---------------------------------------------------------------------------
#define WSTRIDE 140   // float2 row stride, chosen for conflict-free LDS.64
#define SMEM_FLOATS (C_*WSTRIDE*2 + 256)
#define SMEM_BYTES  (SMEM_FLOATS*4)

__global__ void __launch_bounds__(256, 2) gemm_kernel(
    const float* __restrict__ conf,
    const float* __restrict__ w_fc,
    const float* __restrict__ b_fc,
    float* __restrict__ out)
{
    extern __shared__ float sh[];
    float2* whl  = (float2*)sh;            // [64][WSTRIDE] (hi, lo) tf32 pairs
    float*  sw64 = sh + C_*WSTRIDE*2;      // confidence weight row (fp32)
    float*  sb   = sw64 + 128;             // bias

    int tid = threadIdx.x;
    for (int idx = tid; idx < 64*128; idx += 256){
        int k = idx >> 7;
        int n = idx & 127;
        float v = w_fc[k*128 + n];
        uint32_t hb = f2tf32(v);
        float hv = __uint_as_float(hb);
        uint32_t lb = f2tf32(v - hv);
        whl[k*WSTRIDE + n] = make_float2(__uint_as_float(hb), __uint_as_float(lb));
    }
    if (tid < 128){ sw64[tid] = w_fc[64*128 + tid]; sb[tid] = b_fc[tid]; }
    __syncthreads();

    int warp = tid >> 5, lane = tid & 31;
    int g = lane >> 2, tig = lane & 3;
    int r0 = blockIdx.x*128 + warp*16 + g;
    int r1 = r0 + 8;

    // counts: loaded & zeroed by one lane per row group, broadcast via shfl
    float cnt0 = 0.f, cnt1 = 0.f;
    if (tig == 0){
        cnt0 = g_cnt[r0]; cnt1 = g_cnt[r1];
        g_cnt[r0] = 0.f;  g_cnt[r1] = 0.f;
    }
    cnt0 = __shfl_sync(0xffffffffu, cnt0, lane & ~3);
    cnt1 = __shfl_sync(0xffffffffu, cnt1, lane & ~3);
    float inv0 = 1.0f / fmaxf(cnt0, 1.0f);
    float inv1 = 1.0f / fmaxf(cnt1, 1.0f);
    float conf0 = conf[r0];
    float conf1 = conf[r1];

    float c[16][4];
    #pragma unroll
    for (int nt = 0; nt < 16; nt++){
        c[nt][0] = 0.f; c[nt][1] = 0.f; c[nt][2] = 0.f; c[nt][3] = 0.f;
    }

    float* s0 = g_sums + (size_t)r0*64;
    float* s1 = g_sums + (size_t)r1*64;

    #pragma unroll
    for (int kc = 0; kc < 8; kc++){
        int k0 = kc*8;
        // each of these 4 addresses is touched by exactly this thread
        float f0 = s0[k0+tig];
        float f1 = s1[k0+tig];
        float f2 = s0[k0+4+tig];
        float f3 = s1[k0+4+tig];
        s0[k0+tig]   = 0.f;  s1[k0+tig]   = 0.f;
        s0[k0+4+tig] = 0.f;  s1[k0+4+tig] = 0.f;

        float a0f = f0*inv0, a1f = f1*inv1, a2f = f2*inv0, a3f = f3*inv1;
        uint32_t ah0 = f2tf32(a0f), ah1 = f2tf32(a1f);
        uint32_t ah2 = f2tf32(a2f), ah3 = f2tf32(a3f);
        uint32_t al0 = f2tf32(a0f - __uint_as_float(ah0));
        uint32_t al1 = f2tf32(a1f - __uint_as_float(ah1));
        uint32_t al2 = f2tf32(a2f - __uint_as_float(ah2));
        uint32_t al3 = f2tf32(a3f - __uint_as_float(ah3));

        const float2* wrow0 = whl + (k0+tig)*WSTRIDE;
        const float2* wrow1 = whl + (k0+4+tig)*WSTRIDE;
        #pragma unroll
        for (int nt = 0; nt < 16; nt++){
            float2 w0 = wrow0[nt*8 + g];
            float2 w1 = wrow1[nt*8 + g];
            uint32_t bh0 = __float_as_uint(w0.x), bl0 = __float_as_uint(w0.y);
            uint32_t bh1 = __float_as_uint(w1.x), bl1 = __float_as_uint(w1.y);
            MMA_TF32(c[nt], ah0,ah1,ah2,ah3, bh0,bh1);  // hi*hi
            MMA_TF32(c[nt], al0,al1,al2,al3, bh0,bh1);  // lo*hi
            MMA_TF32(c[nt], ah0,ah1,ah2,ah3, bl0,bl1);  // hi*lo
        }
    }

    float* o0 = out + (size_t)r0*128;
    float* o1 = out + (size_t)r1*128;
    #pragma unroll
    for (int nt = 0; nt < 16; nt++){
        int col = nt*8 + 2*tig;
        float w0 = sw64[col],  w1 = sw64[col+1];
        float bv0 = sb[col],   bv1 = sb[col+1];
        float2 v0 = make_float2(c[nt][0] + conf0*w0 + bv0,
                                c[nt][1] + conf0*w1 + bv1);
        float2 v1 = make_float2(c[nt][2] + conf1*w0 + bv0,
                                c[nt][3] + conf1*w1 + bv1);
        *(float2*)(o0 + col) = v0;
        *(float2*)(o1 + col) = v1;
    }
}

// ---------------------------------------------------------------------------
extern "C" void kernel_launch(void* const* d_in, const int* in_sizes, int n_in,
                              void* d_out, int out_size)
{
    (void)in_sizes; (void)n_in; (void)out_size;
    const float*    pose = (const float*)d_in[0];
    const float*    intr = (const float*)d_in[1];
    const float*    feat = (const float*)d_in[2];
    /* d_in[3] = depths, unused by the reference */
    const float*    conf = (const float*)d_in[4];
    const int*      vids = (const int*)d_in[5];
    const unsigned* mask = (const unsigned*)d_in[6];
    const float*    w_fc = (const float*)d_in[7];
    const float*    b_fc = (const float*)d_in[8];

    float* out  = (float*)d_out;                      // (B,V,OUT) first
    float* dout = out + (size_t)ROWS_*OUT_;           // then (B,N,H,W,3)

    int nthreads = 256;
    int nblk = (B_*R_ + nthreads - 1) / nthreads;     // 3072

    rays_kernel<<<nblk, nthreads>>>(pose, intr, dout);

    dim3 sg(nblk, 4);
    scatter_kernel<<<sg, nthreads>>>(feat, vids, mask);

    cudaFuncSetAttribute(gemm_kernel,
                         cudaFuncAttributeMaxDynamicSharedMemorySize, SMEM_BYTES);
    gemm_kernel<<<ROWS_/128, 256, SMEM_BYTES>>>(conf, w_fc, b_fc, out);
}

// round 7
// speedup vs baseline: 1.2760x; 1.2760x over previous
#include <cuda_runtime.h>
#include <cstdint>

#define B_   2
#define N_   8
#define C_   64
#define H_   192
#define W_   256
#define V_   200000
#define HW_  (H_*W_)
#define R_   (N_*HW_)          // 393216
#define ROWS_ (B_*V_)          // 400000
#define OUT_ 128

// Scratch: zero-initialized at module load; the GEMM kernel re-zeroes exactly
// what it reads, so every kernel_launch invocation sees clean state.
__device__ __align__(16) float g_sums[(size_t)ROWS_*C_];   // 102.4 MB
__device__ float g_cnt[ROWS_];

__device__ __forceinline__ uint32_t f2tf32(float x){
    uint32_t r;
    asm("cvt.rna.tf32.f32 %0, %1;" : "=r"(r) : "f"(x));
    return r;
}

#define MMA_TF32(c, a0,a1,a2,a3, b0,b1)                                       \
    asm volatile("mma.sync.aligned.m16n8k8.row.col.f32.tf32.tf32.f32 "        \
        "{%0,%1,%2,%3}, {%4,%5,%6,%7}, {%8,%9}, {%0,%1,%2,%3};"               \
        : "+f"((c)[0]), "+f"((c)[1]), "+f"((c)[2]), "+f"((c)[3])              \
        : "r"(a0), "r"(a1), "r"(a2), "r"(a3), "r"(b0), "r"(b1))

// ---------------------------------------------------------------------------
// Kernel 1: ray directions.
// ---------------------------------------------------------------------------
__global__ void rays_kernel(const float* __restrict__ pose,
                            const float* __restrict__ intr,
                            float* __restrict__ dout)
{
    int i = blockIdx.x*blockDim.x + threadIdx.x;
    if (i >= B_*R_) return;
    int w  = i % W_;
    int h  = (i / W_) % H_;
    int bn = i / HW_;                 // b*N + n
    const float* p  = pose + bn*16;
    const float* it = intr + bn*6;
    float uu = ((float)w - it[2]) / it[0];
    float vv = ((float)h - it[3]) / it[1];
    float dx = p[0]*uu + p[1]*vv + p[2];
    float dy = p[4]*uu + p[5]*vv + p[6];
    float dz = p[8]*uu + p[9]*vv + p[10];
    float rn = rsqrtf(dx*dx + dy*dy + dz*dz);
    dout[3*i+0] = dx*rn;
    dout[3*i+1] = dy*rn;
    dout[3*i+2] = dz*rn;
}

// ---------------------------------------------------------------------------
// Kernel 2: masked scatter-add. One thread per pixel handles all 64 channels
// (channel stride = HW_, so warp-adjacent threads = adjacent pixels stay
// fully coalesced for every channel load). 16x red.v4 per hit pixel.
// ---------------------------------------------------------------------------
__global__ void scatter_kernel(const float* __restrict__ feat,
                               const int*   __restrict__ vids,
                               const unsigned* __restrict__ mask)
{
    int idx = blockIdx.x*blockDim.x + threadIdx.x;
    if (idx >= B_*R_) return;
    if (mask[idx] == 0u) return;          // float32 1.0 or int32 1 both nonzero
    int b   = idx / R_;
    int vid = vids[idx];
    atomicAdd(&g_cnt[b*V_ + vid], 1.0f);
    int bn = idx / HW_;
    int hw = idx % HW_;
    const float* fp = feat + (size_t)bn*C_*HW_ + hw;
    float* sp = g_sums + (size_t)(b*V_ + vid)*C_;
    #pragma unroll
    for (int cg = 0; cg < 16; cg++){
        float x0 = fp[(size_t)(4*cg+0)*HW_];
        float x1 = fp[(size_t)(4*cg+1)*HW_];
        float x2 = fp[(size_t)(4*cg+2)*HW_];
        float x3 = fp[(size_t)(4*cg+3)*HW_];
        asm volatile("red.global.add.v4.f32 [%0], {%1, %2, %3, %4};"
                     :: "l"(sp + 4*cg), "f"(x0), "f"(x1), "f"(x2), "f"(x3)
                     : "memory");
    }
}

// ---------------------------------------------------------------------------
// Kernel 3: out[row,:] = (sums/max(cnt,1)) @ W[0:64,:] + conf*W[64,:] + b.
// 128 threads = 4 warps; each warp owns 32 rows (two 16-row m-tiles sharing
// the same B fragments -> B LDS traffic per row halved vs 16-row warps).
// A tile is staged through shared with coalesced LDG.128 and zeroed back
// with coalesced STG.128. tf32 hi/lo 3-pass => fp32-grade accuracy.
// ---------------------------------------------------------------------------
#define WSTRIDE 140                        // float2 units, conflict-free LDS.64
#define ASTRIDE 68                         // float units, conflict-free frags
#define SA_OFF   (C_*WSTRIDE*2)            // 17920 floats
#define SCNT_OFF (SA_OFF + 128*ASTRIDE)    // 26624
#define SMEM_FLOATS (SCNT_OFF + 512)       // scnt,sconf,sw64,sb (128 each)
#define SMEM_BYTES  (SMEM_FLOATS*4)        // 108544 B

__global__ void __launch_bounds__(128, 2) gemm_kernel(
    const float* __restrict__ conf,
    const float* __restrict__ w_fc,
    const float* __restrict__ b_fc,
    float* __restrict__ out)
{
    extern __shared__ float sh[];
    float2* whl  = (float2*)sh;            // [64][WSTRIDE] (hi,lo) tf32 pairs
    float*  sA   = sh + SA_OFF;            // [128][ASTRIDE]
    float*  scnt = sh + SCNT_OFF;          // 1/max(cnt,1), 128 rows
    float*  sconf= scnt + 128;
    float*  sw64 = sconf + 128;
    float*  sb   = sw64 + 128;

    int tid = threadIdx.x;
    size_t rowbase = (size_t)blockIdx.x * 128;

    // --- stage weights (hi/lo tf32 split) ---
    #pragma unroll 4
    for (int idx = tid; idx < 64*128; idx += 128){
        int k = idx >> 7, n = idx & 127;
        float v = w_fc[idx];
        uint32_t hb = f2tf32(v);
        uint32_t lb = f2tf32(v - __uint_as_float(hb));
        whl[k*WSTRIDE + n] = make_float2(__uint_as_float(hb), __uint_as_float(lb));
    }
    // --- stage per-row scalars (coalesced), reset g_cnt ---
    {
        sw64[tid] = w_fc[64*128 + tid];
        sb[tid]   = b_fc[tid];
        float cv  = g_cnt[rowbase + tid];
        g_cnt[rowbase + tid] = 0.0f;
        scnt[tid] = 1.0f / fmaxf(cv, 1.0f);
        sconf[tid]= conf[rowbase + tid];
    }
    // --- stage A tile (coalesced 128-bit) and zero g_sums back ---
    {
        float4* gp = (float4*)(g_sums + rowbase*C_);
        float4 z = make_float4(0.f, 0.f, 0.f, 0.f);
        #pragma unroll
        for (int it = 0; it < 16; it++){
            int i = it*128 + tid;          // 2048 float4 total
            float4 v = gp[i];
            int r = i >> 4, c4 = i & 15;
            *(float4*)&sA[r*ASTRIDE + c4*4] = v;
            gp[i] = z;
        }
    }
    __syncthreads();

    int warp = tid >> 5, lane = tid & 31;
    int g = lane >> 2, tig = lane & 3;
    int lr0 = warp*32 + g;                 // rows lr0, +8, +16, +24

    float inv00 = scnt[lr0],      inv01 = scnt[lr0 + 8];
    float inv10 = scnt[lr0 + 16], inv11 = scnt[lr0 + 24];

    float c[2][16][4];
    #pragma unroll
    for (int mt = 0; mt < 2; mt++)
        #pragma unroll
        for (int nt = 0; nt < 16; nt++){
            c[mt][nt][0]=0.f; c[mt][nt][1]=0.f; c[mt][nt][2]=0.f; c[mt][nt][3]=0.f;
        }

    #pragma unroll
    for (int kc = 0; kc < 8; kc++){
        int k0 = kc*8;
        // A fragments (conflict-free: bank = g*4+tig), scaled by 1/cnt
        float a00 = sA[(lr0   )*ASTRIDE + k0 +   tig] * inv00;
        float a01 = sA[(lr0+ 8)*ASTRIDE + k0 +   tig] * inv01;
        float a02 = sA[(lr0   )*ASTRIDE + k0+4+ tig] * inv00;
        float a03 = sA[(lr0+ 8)*ASTRIDE + k0+4+ tig] * inv01;
        float a10 = sA[(lr0+16)*ASTRIDE + k0 +   tig] * inv10;
        float a11 = sA[(lr0+24)*ASTRIDE + k0 +   tig] * inv11;
        float a12 = sA[(lr0+16)*ASTRIDE + k0+4+ tig] * inv10;
        float a13 = sA[(lr0+24)*ASTRIDE + k0+4+ tig] * inv11;

        uint32_t ah[2][4], al[2][4];
        ah[0][0]=f2tf32(a00); ah[0][1]=f2tf32(a01); ah[0][2]=f2tf32(a02); ah[0][3]=f2tf32(a03);
        ah[1][0]=f2tf32(a10); ah[1][1]=f2tf32(a11); ah[1][2]=f2tf32(a12); ah[1][3]=f2tf32(a13);
        al[0][0]=f2tf32(a00-__uint_as_float(ah[0][0]));
        al[0][1]=f2tf32(a01-__uint_as_float(ah[0][1]));
        al[0][2]=f2tf32(a02-__uint_as_float(ah[0][2]));
        al[0][3]=f2tf32(a03-__uint_as_float(ah[0][3]));
        al[1][0]=f2tf32(a10-__uint_as_float(ah[1][0]));
        al[1][1]=f2tf32(a11-__uint_as_float(ah[1][1]));
        al[1][2]=f2tf32(a12-__uint_as_float(ah[1][2]));
        al[1][3]=f2tf32(a13-__uint_as_float(ah[1][3]));

        const float2* wrow0 = whl + (k0+tig)*WSTRIDE;
        const float2* wrow1 = whl + (k0+4+tig)*WSTRIDE;
        #pragma unroll
        for (int nt = 0; nt < 16; nt++){
            float2 w0 = wrow0[nt*8 + g];
            float2 w1 = wrow1[nt*8 + g];
            uint32_t bh0 = __float_as_uint(w0.x), bl0 = __float_as_uint(w0.y);
            uint32_t bh1 = __float_as_uint(w1.x), bl1 = __float_as_uint(w1.y);
            MMA_TF32(c[0][nt], ah[0][0],ah[0][1],ah[0][2],ah[0][3], bh0,bh1);
            MMA_TF32(c[0][nt], al[0][0],al[0][1],al[0][2],al[0][3], bh0,bh1);
            MMA_TF32(c[0][nt], ah[0][0],ah[0][1],ah[0][2],ah[0][3], bl0,bl1);
            MMA_TF32(c[1][nt], ah[1][0],ah[1][1],ah[1][2],ah[1][3], bh0,bh1);
            MMA_TF32(c[1][nt], al[1][0],al[1][1],al[1][2],al[1][3], bh0,bh1);
            MMA_TF32(c[1][nt], ah[1][0],ah[1][1],ah[1][2],ah[1][3], bl0,bl1);
        }
    }

    // --- epilogue: + conf*W[64,:] + bias, float2 stores (full 32B sectors) ---
    #pragma unroll
    for (int mt = 0; mt < 2; mt++){
        int lrow0 = lr0 + mt*16;
        int lrow1 = lrow0 + 8;
        float conf0 = sconf[lrow0], conf1 = sconf[lrow1];
        float* o0 = out + (rowbase + lrow0)*128;
        float* o1 = out + (rowbase + lrow1)*128;
        #pragma unroll
        for (int nt = 0; nt < 16; nt++){
            int col = nt*8 + 2*tig;
            float w0 = sw64[col],  w1 = sw64[col+1];
            float bv0 = sb[col],   bv1 = sb[col+1];
            float2 v0 = make_float2(c[mt][nt][0] + conf0*w0 + bv0,
                                    c[mt][nt][1] + conf0*w1 + bv1);
            float2 v1 = make_float2(c[mt][nt][2] + conf1*w0 + bv0,
                                    c[mt][nt][3] + conf1*w1 + bv1);
            *(float2*)(o0 + col) = v0;
            *(float2*)(o1 + col) = v1;
        }
    }
}

// ---------------------------------------------------------------------------
extern "C" void kernel_launch(void* const* d_in, const int* in_sizes, int n_in,
                              void* d_out, int out_size)
{
    (void)in_sizes; (void)n_in; (void)out_size;
    const float*    pose = (const float*)d_in[0];
    const float*    intr = (const float*)d_in[1];
    const float*    feat = (const float*)d_in[2];
    /* d_in[3] = depths, unused by the reference */
    const float*    conf = (const float*)d_in[4];
    const int*      vids = (const int*)d_in[5];
    const unsigned* mask = (const unsigned*)d_in[6];
    const float*    w_fc = (const float*)d_in[7];
    const float*    b_fc = (const float*)d_in[8];

    float* out  = (float*)d_out;                      // (B,V,OUT) first
    float* dout = out + (size_t)ROWS_*OUT_;           // then (B,N,H,W,3)

    int nblk = (B_*R_ + 255) / 256;                   // 3072

    rays_kernel<<<nblk, 256>>>(pose, intr, dout);
    scatter_kernel<<<nblk, 256>>>(feat, vids, mask);

    cudaFuncSetAttribute(gemm_kernel,
                         cudaFuncAttributeMaxDynamicSharedMemorySize, SMEM_BYTES);
    gemm_kernel<<<ROWS_/128, 128, SMEM_BYTES>>>(conf, w_fc, b_fc, out);
}